// round 10
// baseline (speedup 1.0000x reference)
#include <cuda_runtime.h>
#include <cstdint>
#include <cstddef>

// Problem constants (fixed by the reference).
#define Bb   2
#define Hh   16
#define Ss   2048
#define Dd   64
#define TQ   16          // queries per CTA
#define TK   8           // keys per k-tile
#define NKT  (Ss / TK)   // 256 k-tiles
#define NTH  512         // 16 heads x 16 queries x 2 d-halves

typedef unsigned long long u64;

// Padded smem row layout for K/V tiles (conflict-free 16B broadcast loads).
#define ROWP  (TK * Dd + 4)        // 516 floats per head per buffer
#define KVBUF (Hh * ROWP)          // 8256 floats per buffer
#define SSTR  145                  // Ssh head stride (odd -> softmax bank spread)

__device__ __forceinline__ void ffma2(u64& acc, u64 a, u64 b) {
    asm volatile("fma.rn.f32x2 %0, %1, %2, %0;" : "+l"(acc) : "l"(a), "l"(b));
}
__device__ __forceinline__ u64 mul2(u64 a, u64 b) {
    u64 r; asm("mul.rn.f32x2 %0, %1, %2;" : "=l"(r) : "l"(a), "l"(b)); return r;
}
__device__ __forceinline__ u64 pack2(float lo, float hi) {
    u64 r; asm("mov.b64 %0, {%1,%2};" : "=l"(r) : "f"(lo), "f"(hi)); return r;
}
__device__ __forceinline__ void unpack2(u64 v, float& lo, float& hi) {
    asm("mov.b64 {%0,%1}, %2;" : "=f"(lo), "=f"(hi) : "l"(v));
}
__device__ __forceinline__ void cp16(float* sdst, const float* gsrc) {
    uint32_t sa = (uint32_t)__cvta_generic_to_shared(sdst);
    asm volatile("cp.async.cg.shared.global [%0], [%1], 16;" :: "r"(sa), "l"(gsrc));
}
__device__ __forceinline__ void cp_commit() { asm volatile("cp.async.commit_group;"); }
template <int N>
__device__ __forceinline__ void cp_wait() { asm volatile("cp.async.wait_group %0;" :: "n"(N)); }

__device__ __forceinline__ float neg_inf() { return __int_as_float(0xff800000); }

// ---------------------------------------------------------------------------
// Mask storage detection (harness normalizes dtypes; bool is not a wire type).
// Only the ELEMENT SIZE matters downstream: "masked" == nonzero bits.
// ---------------------------------------------------------------------------
__device__ int g_mask_esz;   // 1, 2, or 4 bytes per mask element

#define F_BYTE_HI  1
#define F_NOT01B   2
#define F_NOTF32   4
#define F_NOTBF16  8

__global__ void detect_mask_kernel(const uint32_t* __restrict__ m, int nwords) {
    __shared__ int sflags;
    if (threadIdx.x == 0) sflags = 0;
    __syncthreads();
    int f = 0;
    for (int i = threadIdx.x; i < nwords; i += blockDim.x) {
        uint32_t w = m[i];
        if (w & 0xFFFFFF00u) f |= F_BYTE_HI;
        #pragma unroll
        for (int j = 0; j < 4; j++) {
            uint32_t byt = (w >> (8 * j)) & 0xffu;
            if (byt > 1u) f |= F_NOT01B;
        }
        if (w != 0u && w != 0x3f800000u) f |= F_NOTF32;
        uint32_t lo = w & 0xffffu, hi = w >> 16;
        if ((lo != 0u && lo != 0x3f80u) || (hi != 0u && hi != 0x3f80u)) f |= F_NOTBF16;
    }
    atomicOr(&sflags, f);
    __syncthreads();
    if (threadIdx.x == 0) {
        int ff = sflags;
        int esz;
        if (!(ff & F_BYTE_HI))      esz = 4;  // int32 0/1
        else if (!(ff & F_NOT01B))  esz = 1;  // byte-packed bool
        else if (!(ff & F_NOTF32))  esz = 4;  // float32 0/1
        else if (!(ff & F_NOTBF16)) esz = 2;  // bf16
        else                        esz = 1;  // fallback
        g_mask_esz = esz;
    }
}

// smem (floats): Kb[2*KVBUF] | Vb[2*KVBUF] | Ssh[Hh*SSTR] | MRsh[144 float2]
#define SMEM_FLOATS (2 * KVBUF + 2 * KVBUF + Hh * SSTR + 2 * (TQ * 9))

__global__ void __launch_bounds__(NTH, 1)
attn_head_softmax_kernel(const float* __restrict__ Qg,
                         const float* __restrict__ Kg,
                         const float* __restrict__ Vg,
                         const unsigned char* __restrict__ Mg,
                         float* __restrict__ Og)
{
    extern __shared__ float smem[];
    float*  Kb   = smem;                       // 2 * 8256
    float*  Vb   = Kb + 2 * KVBUF;             // 2 * 8256
    float*  Ssh  = Vb + 2 * KVBUF;             // 16 * 145
    float2* MRsh = reinterpret_cast<float2*>(Ssh + Hh * SSTR);   // 144 float2

    const int b  = blockIdx.y;
    const int q0 = blockIdx.x * TQ;
    const int t  = threadIdx.x;
    const int h  = t >> 5;           // warp id == head (0..15)
    const int q  = (t >> 1) & 15;    // 0..15
    const int dh = t & 1;            // d-split: INTERLEAVED 16B chunks
    const int dhb = dh * 16;         // byte offset of this thread's chunk in a 32B pair

    const int esz = g_mask_esz;      // uniform

    // ---- this thread's 32 Q dims (chunks i*32B + dhb), pre-scaled by 1/8 ----
    u64 Qp[16];
    {
        const char* qbase = reinterpret_cast<const char*>(
            Qg + ((size_t)(b * Hh + h) * Ss + (q0 + q)) * Dd);
        const u64 sc = pack2(0.125f, 0.125f);
        #pragma unroll
        for (int i = 0; i < 8; i++) {
            ulonglong2 v = *reinterpret_cast<const ulonglong2*>(qbase + i * 32 + dhb);
            Qp[2*i]   = mul2(v.x, sc);
            Qp[2*i+1] = mul2(v.y, sc);
        }
    }

    // ---- context accumulator: 32 fp32 as 16 packed f32x2 ----
    u64 ctx[16];
    #pragma unroll
    for (int i = 0; i < 16; i++) ctx[i] = 0ull;

    // Mask row base in BYTES (only dh==0 threads touch it).
    const unsigned char* mrow =
        Mg + ((size_t)(b * Hh + h) * Ss + (q0 + q)) * (size_t)Ss * (size_t)esz;

    // ---- loaders: 2048 float4 per matrix over 512 threads = 4 each ----
    auto loadK = [&](int kt, int buf) {
        const int k0 = kt * TK;
        #pragma unroll
        for (int j = 0; j < 4; j++) {
            int i   = t + j * NTH;
            int row = i >> 4, d4 = i & 15;
            int h2  = row >> 3, kk = row & 7;
            size_t goff = ((size_t)(b * Hh + h2) * Ss + (k0 + kk)) * Dd + d4 * 4;
            cp16(&Kb[buf * KVBUF + h2 * ROWP + kk * Dd + d4 * 4], Kg + goff);
        }
    };
    auto loadV = [&](int kt, int buf) {
        const int k0 = kt * TK;
        #pragma unroll
        for (int j = 0; j < 4; j++) {
            int i   = t + j * NTH;
            int row = i >> 4, d4 = i & 15;
            int h2  = row >> 3, kk = row & 7;
            size_t goff = ((size_t)(b * Hh + h2) * Ss + (k0 + kk)) * Dd + d4 * 4;
            cp16(&Vb[buf * KVBUF + h2 * ROWP + kk * Dd + d4 * 4], Vg + goff);
        }
    };

    // ---- mask fetch for 8 keys of a tile (dh==0 lanes; dtype-agnostic) ----
    auto load_mask = [&](int kt) -> unsigned {
        if (dh != 0) return 0u;
        const int k0 = kt * TK;
        unsigned mk = 0;
        if (esz == 4) {
            const uint4* p = reinterpret_cast<const uint4*>(mrow + (size_t)k0 * 4);
            uint4 a = p[0], c = p[1];
            mk = (a.x ? 1u : 0u) | (a.y ? 2u : 0u) | (a.z ? 4u : 0u) | (a.w ? 8u : 0u)
               | (c.x ? 16u : 0u) | (c.y ? 32u : 0u) | (c.z ? 64u : 0u) | (c.w ? 128u : 0u);
        } else if (esz == 1) {
            u64 v = *reinterpret_cast<const u64*>(mrow + k0);
            #pragma unroll
            for (int j = 0; j < 8; j++)
                if ((v >> (8 * j)) & 0xffull) mk |= (1u << j);
        } else {
            uint4 a = *reinterpret_cast<const uint4*>(mrow + (size_t)k0 * 2);
            uint32_t w[4] = {a.x, a.y, a.z, a.w};
            #pragma unroll
            for (int j = 0; j < 4; j++) {
                if (w[j] & 0xffffu) mk |= (1u << (2 * j));
                if (w[j] >> 16)     mk |= (1u << (2 * j + 1));
            }
        }
        return mk;
    };

    float sreg[TK];

    // ---- score for one tile out of K buffer kb: writes sreg + Ssh ----
    auto do_score = [&](int kb, unsigned mk) {
        #pragma unroll
        for (int kk = 0; kk < TK; kk++) {
            const char* kbp = reinterpret_cast<const char*>(
                &Kb[kb * KVBUF + h * ROWP + kk * Dd]);
            u64 a0 = 0ull, a1 = 0ull;
            #pragma unroll
            for (int i = 0; i < 8; i++) {
                ulonglong2 kv = *reinterpret_cast<const ulonglong2*>(kbp + i * 32 + dhb);
                ffma2(a0, Qp[2*i],   kv.x);
                ffma2(a1, Qp[2*i+1], kv.y);
            }
            float l0, h0, l1, h1; unpack2(a0, l0, h0); unpack2(a1, l1, h1);
            float part = (l0 + h0) + (l1 + h1);
            if ((mk >> kk) & 1u) part = neg_inf();
            float s = part + __shfl_xor_sync(0xffffffffu, part, 1);
            sreg[kk] = s;
            if (dh == 0) Ssh[h * SSTR + q * 9 + kk] = s;
        }
    };

    // =================== prologue ===================
    loadK(0, 0); cp_commit();
    cp_wait<0>(); __syncthreads();
    loadV(0, 0); loadK(1, 1); cp_commit();      // overlaps score(0)
    unsigned mkv = load_mask(0);
    do_score(0, mkv);                            // scores of tile 0 -> Ssh, sreg
    mkv = load_mask(1);                          // mask for tile 1 (next scored)

    // =================== main loop ===================
    for (int cur = 0; cur < NKT; cur++) {
        __syncthreads();                         // (S) Ssh(cur) ready

        // ---- head softmax over 16 h: ALL 512 threads, 4 heads each ----
        {
            const int item = t >> 2, sub = t & 3;
            const int q2 = item >> 3, kk2 = item & 7;
            const int sb = q2 * 9 + kk2;
            const int hbase = sub * 4;
            float s0 = Ssh[(hbase + 0) * SSTR + sb];
            float s1 = Ssh[(hbase + 1) * SSTR + sb];
            float s2 = Ssh[(hbase + 2) * SSTR + sb];
            float s3 = Ssh[(hbase + 3) * SSTR + sb];
            float m = fmaxf(fmaxf(s0, s1), fmaxf(s2, s3));
            m = fmaxf(m, __shfl_xor_sync(0xffffffffu, m, 1));
            m = fmaxf(m, __shfl_xor_sync(0xffffffffu, m, 2));
            float e = __expf(s0 - m) + __expf(s1 - m) + __expf(s2 - m) + __expf(s3 - m);
            e += __shfl_xor_sync(0xffffffffu, e, 1);
            e += __shfl_xor_sync(0xffffffffu, e, 2);
            if (sub == 0) {
                float2 mr;
                if (m == neg_inf()) { mr.x = 0.f; mr.y = 0.f; }
                else                { mr.x = m;   mr.y = 1.0f / e; }
                MRsh[sb] = mr;
            }
        }

        cp_wait<0>();                            // V[cur], K[cur+1] resident
        __syncthreads();                         // (W) weights + tiles visible

        // ---- prefetch next tiles + next-next mask (hidden under fused phase) ----
        const int nb = (cur + 1) & 1;            // buffer of K[cur+1]; target of V[cur+1]
        if (cur + 1 < NKT) loadV(cur + 1, nb);
        if (cur + 2 < NKT) loadK(cur + 2, cur & 1);
        cp_commit();
        unsigned mknext = (cur + 2 < NKT) ? load_mask(cur + 2) : 0u;

        // ---- fused phase: ctx(cur) + score(cur+1) ----
        const int vb = cur & 1;
        const bool do_sc = (cur + 1 < NKT);
        #pragma unroll
        for (int kk = 0; kk < TK; kk++) {
            // ctx(cur), key kk: consume old sreg[kk]
            float2 mr = MRsh[q * 9 + kk];
            float w = __expf(sreg[kk] - mr.x) * mr.y;
            u64 wp = pack2(w, w);
            const char* vbp = reinterpret_cast<const char*>(
                &Vb[vb * KVBUF + h * ROWP + kk * Dd]);
            #pragma unroll
            for (int i = 0; i < 8; i++) {
                ulonglong2 vv = *reinterpret_cast<const ulonglong2*>(vbp + i * 32 + dhb);
                ffma2(ctx[2*i],   wp, vv.x);
                ffma2(ctx[2*i+1], wp, vv.y);
            }
            // score(cur+1), key kk: independent stream, interleaves with ctx
            if (do_sc) {
                const char* kbp = reinterpret_cast<const char*>(
                    &Kb[nb * KVBUF + h * ROWP + kk * Dd]);
                u64 a0 = 0ull, a1 = 0ull;
                #pragma unroll
                for (int i = 0; i < 8; i++) {
                    ulonglong2 kv = *reinterpret_cast<const ulonglong2*>(kbp + i * 32 + dhb);
                    ffma2(a0, Qp[2*i],   kv.x);
                    ffma2(a1, Qp[2*i+1], kv.y);
                }
                float l0, h0, l1, h1; unpack2(a0, l0, h0); unpack2(a1, l1, h1);
                float part = (l0 + h0) + (l1 + h1);
                if ((mkv >> kk) & 1u) part = neg_inf();
                float s = part + __shfl_xor_sync(0xffffffffu, part, 1);
                sreg[kk] = s;
                if (dh == 0) Ssh[h * SSTR + q * 9 + kk] = s;
            }
        }
        mkv = mknext;
    }

    // ---- epilogue: out[b, q0+q, h, chunks i*32B + dhb] = ctx ----
    char* obase = reinterpret_cast<char*>(
        Og + ((size_t)(b * Ss + (q0 + q)) * Hh + h) * Dd);
    #pragma unroll
    for (int i = 0; i < 8; i++) {
        ulonglong2 v; v.x = ctx[2*i]; v.y = ctx[2*i+1];
        *reinterpret_cast<ulonglong2*>(obase + i * 32 + dhb) = v;
    }
}

extern "C" void kernel_launch(void* const* d_in, const int* in_sizes, int n_in,
                              void* d_out, int out_size) {
    const float*         Q = (const float*)d_in[0];
    const float*         K = (const float*)d_in[1];
    const float*         V = (const float*)d_in[2];
    const unsigned char* M = (const unsigned char*)d_in[3];   // mask, dtype detected on-device
    // d_in[4] = head_dim (compile-time 64); unused.
    float* O = (float*)d_out;

    // 1) classify mask storage (element size). 256 KB sample, deterministic.
    detect_mask_kernel<<<1, 256>>>((const uint32_t*)M, 1 << 16);

    // 2) main attention kernel
    const size_t smem_bytes = (size_t)SMEM_FLOATS * sizeof(float);  // ~142 KB
    cudaFuncSetAttribute(attn_head_softmax_kernel,
                         cudaFuncAttributeMaxDynamicSharedMemorySize,
                         (int)smem_bytes);

    dim3 grid(Ss / TQ, Bb);   // (128, 2) = 256 CTAs of 512 threads
    attn_head_softmax_kernel<<<grid, NTH, smem_bytes>>>(Q, K, V, M, O);
}

// round 12
// speedup vs baseline: 1.1353x; 1.1353x over previous
#include <cuda_runtime.h>
#include <cstdint>
#include <cstddef>

// Problem constants (fixed by the reference).
#define Bb   2
#define Hh   16
#define Ss   2048
#define Dd   64
#define TQ   16          // queries per CTA
#define TK   8           // keys per k-tile
#define NKT  (Ss / TK)   // 256 k-tiles
#define NTH  512         // 16 heads x 16 queries x 2 d-halves

typedef unsigned long long u64;

// Unpadded smem rows: bulk copies are contiguous; warp = one head so LDS
// conflicts don't depend on the head stride anymore.
#define ROWF   (TK * Dd)           // 512 floats per head per buffer (2 KB)
#define KVBUF  (Hh * ROWF)         // 8192 floats per buffer (32 KB)
#define SSTR   145                 // Ssh head stride (odd -> softmax bank spread)
#define TILEB  (Hh * TK * Dd * 4)  // 32768 bytes per K or V tile

__device__ __forceinline__ void ffma2(u64& acc, u64 a, u64 b) {
    asm volatile("fma.rn.f32x2 %0, %1, %2, %0;" : "+l"(acc) : "l"(a), "l"(b));
}
__device__ __forceinline__ u64 mul2(u64 a, u64 b) {
    u64 r; asm("mul.rn.f32x2 %0, %1, %2;" : "=l"(r) : "l"(a), "l"(b)); return r;
}
__device__ __forceinline__ u64 pack2(float lo, float hi) {
    u64 r; asm("mov.b64 %0, {%1,%2};" : "=l"(r) : "f"(lo), "f"(hi)); return r;
}
__device__ __forceinline__ void unpack2(u64 v, float& lo, float& hi) {
    asm("mov.b64 {%0,%1}, %2;" : "=f"(lo), "=f"(hi) : "l"(v));
}
__device__ __forceinline__ float neg_inf() { return __int_as_float(0xff800000); }

// ---- bulk-copy + mbarrier primitives ----
__device__ __forceinline__ uint32_t s2u(const void* p) {
    return (uint32_t)__cvta_generic_to_shared(p);
}
__device__ __forceinline__ void mbar_init(uint32_t mbar, uint32_t cnt) {
    asm volatile("mbarrier.init.shared::cta.b64 [%0], %1;" :: "r"(mbar), "r"(cnt) : "memory");
}
__device__ __forceinline__ void mbar_expect(uint32_t mbar, uint32_t bytes) {
    asm volatile("mbarrier.arrive.expect_tx.shared::cta.b64 _, [%0], %1;"
                 :: "r"(mbar), "r"(bytes) : "memory");
}
__device__ __forceinline__ void mbar_wait(uint32_t mbar, uint32_t phase) {
    asm volatile(
        "{\n\t"
        ".reg .pred P;\n\t"
        "LAB_%=:\n\t"
        "mbarrier.try_wait.parity.acquire.cta.shared::cta.b64 P, [%0], %1, 0x989680;\n\t"
        "@P bra DONE_%=;\n\t"
        "bra LAB_%=;\n\t"
        "DONE_%=:\n\t"
        "}"
        :: "r"(mbar), "r"(phase) : "memory");
}
__device__ __forceinline__ void bulk_g2s(uint32_t sdst, const void* gsrc,
                                         uint32_t bytes, uint32_t mbar) {
    asm volatile(
        "cp.async.bulk.shared::cta.global.mbarrier::complete_tx::bytes [%0], [%1], %2, [%3];"
        :: "r"(sdst), "l"(gsrc), "r"(bytes), "r"(mbar) : "memory");
}

// ---------------------------------------------------------------------------
// Mask storage detection (harness normalizes dtypes; bool is not a wire type).
// Only the ELEMENT SIZE matters downstream: "masked" == nonzero bits.
// ---------------------------------------------------------------------------
__device__ int g_mask_esz;   // 1, 2, or 4 bytes per mask element

#define F_BYTE_HI  1
#define F_NOT01B   2
#define F_NOTF32   4
#define F_NOTBF16  8

__global__ void detect_mask_kernel(const uint32_t* __restrict__ m, int nwords) {
    __shared__ int sflags;
    if (threadIdx.x == 0) sflags = 0;
    __syncthreads();
    int f = 0;
    for (int i = threadIdx.x; i < nwords; i += blockDim.x) {
        uint32_t w = m[i];
        if (w & 0xFFFFFF00u) f |= F_BYTE_HI;
        #pragma unroll
        for (int j = 0; j < 4; j++) {
            uint32_t byt = (w >> (8 * j)) & 0xffu;
            if (byt > 1u) f |= F_NOT01B;
        }
        if (w != 0u && w != 0x3f800000u) f |= F_NOTF32;
        uint32_t lo = w & 0xffffu, hi = w >> 16;
        if ((lo != 0u && lo != 0x3f80u) || (hi != 0u && hi != 0x3f80u)) f |= F_NOTBF16;
    }
    atomicOr(&sflags, f);
    __syncthreads();
    if (threadIdx.x == 0) {
        int ff = sflags;
        int esz;
        if (!(ff & F_BYTE_HI))      esz = 4;  // int32 0/1
        else if (!(ff & F_NOT01B))  esz = 1;  // byte-packed bool
        else if (!(ff & F_NOTF32))  esz = 4;  // float32 0/1
        else if (!(ff & F_NOTBF16)) esz = 2;  // bf16
        else                        esz = 1;  // fallback
        g_mask_esz = esz;
    }
}

// smem (floats): Kb[2*KVBUF] | Vb[2*KVBUF] | Ssh[Hh*SSTR] | MRsh[144 f2] | mbars
#define SMEM_FLOATS (2 * KVBUF + 2 * KVBUF + Hh * SSTR + 2 * (TQ * 9) + 16)

__global__ void __launch_bounds__(NTH, 1)
attn_head_softmax_kernel(const float* __restrict__ Qg,
                         const float* __restrict__ Kg,
                         const float* __restrict__ Vg,
                         const unsigned char* __restrict__ Mg,
                         float* __restrict__ Og)
{
    extern __shared__ float smem[];
    float*  Kb   = smem;                       // 2 * 8192
    float*  Vb   = Kb + 2 * KVBUF;             // 2 * 8192
    float*  Ssh  = Vb + 2 * KVBUF;             // 16 * 145
    float2* MRsh = reinterpret_cast<float2*>(Ssh + Hh * SSTR);   // 144 float2
    u64*    mbars = reinterpret_cast<u64*>(MRsh + TQ * 9);       // 3 mbarriers

    const uint32_t kbB  = s2u(Kb);
    const uint32_t vbB  = s2u(Vb);
    const uint32_t mb0  = s2u(&mbars[0]);        // prologue K(0)
    const uint32_t mbG0 = s2u(&mbars[1]);        // group barriers (parity 0/1)
    const uint32_t mbG1 = s2u(&mbars[2]);

    const int b  = blockIdx.y;
    const int q0 = blockIdx.x * TQ;
    const int t  = threadIdx.x;
    const int h  = t >> 5;           // warp id == head (0..15)
    const int q  = (t >> 1) & 15;    // 0..15
    const int dh = t & 1;            // d-split: INTERLEAVED 16B chunks
    const int dhb = dh * 16;

    const int esz = g_mask_esz;      // uniform

    if (t == 0) { mbar_init(mb0, 1); mbar_init(mbG0, 1); mbar_init(mbG1, 1); }
    __syncthreads();

    // ---- this thread's 32 Q dims (chunks i*32B + dhb), pre-scaled by 1/8 ----
    u64 Qp[16];
    {
        const char* qbase = reinterpret_cast<const char*>(
            Qg + ((size_t)(b * Hh + h) * Ss + (q0 + q)) * Dd);
        const u64 sc = pack2(0.125f, 0.125f);
        #pragma unroll
        for (int i = 0; i < 8; i++) {
            ulonglong2 v = *reinterpret_cast<const ulonglong2*>(qbase + i * 32 + dhb);
            Qp[2*i]   = mul2(v.x, sc);
            Qp[2*i+1] = mul2(v.y, sc);
        }
    }

    u64 ctx[16];
    #pragma unroll
    for (int i = 0; i < 16; i++) ctx[i] = 0ull;

    // Mask row base in BYTES (only dh==0 threads touch it).
    const unsigned char* mrow =
        Mg + ((size_t)(b * Hh + h) * Ss + (q0 + q)) * (size_t)Ss * (size_t)esz;

    // ---- bulk-copy issue: lanes 0..15 -> V heads, 16..31 -> K heads ----
    auto kglob = [&](int h2, int k0) -> const float* {
        return Kg + ((size_t)(b * Hh + h2) * Ss + k0) * Dd;
    };
    auto vglob = [&](int h2, int k0) -> const float* {
        return Vg + ((size_t)(b * Hh + h2) * Ss + k0) * Dd;
    };

    auto load_mask = [&](int kt) -> unsigned {
        if (dh != 0) return 0u;
        const int k0 = kt * TK;
        unsigned mk = 0;
        if (esz == 4) {
            const uint4* p = reinterpret_cast<const uint4*>(mrow + (size_t)k0 * 4);
            uint4 a = p[0], c = p[1];
            mk = (a.x ? 1u : 0u) | (a.y ? 2u : 0u) | (a.z ? 4u : 0u) | (a.w ? 8u : 0u)
               | (c.x ? 16u : 0u) | (c.y ? 32u : 0u) | (c.z ? 64u : 0u) | (c.w ? 128u : 0u);
        } else if (esz == 1) {
            u64 v = *reinterpret_cast<const u64*>(mrow + k0);
            #pragma unroll
            for (int j = 0; j < 8; j++)
                if ((v >> (8 * j)) & 0xffull) mk |= (1u << j);
        } else {
            uint4 a = *reinterpret_cast<const uint4*>(mrow + (size_t)k0 * 2);
            uint32_t w[4] = {a.x, a.y, a.z, a.w};
            #pragma unroll
            for (int j = 0; j < 4; j++) {
                if (w[j] & 0xffffu) mk |= (1u << (2 * j));
                if (w[j] >> 16)     mk |= (1u << (2 * j + 1));
            }
        }
        return mk;
    };

    float sreg[TK];

    auto do_score = [&](int kb, unsigned mk) {
        #pragma unroll
        for (int kk = 0; kk < TK; kk++) {
            const char* kbp = reinterpret_cast<const char*>(
                &Kb[kb * KVBUF + h * ROWF + kk * Dd]);
            u64 a0 = 0ull, a1 = 0ull;
            #pragma unroll
            for (int i = 0; i < 8; i++) {
                ulonglong2 kv = *reinterpret_cast<const ulonglong2*>(kbp + i * 32 + dhb);
                ffma2(a0, Qp[2*i],   kv.x);
                ffma2(a1, Qp[2*i+1], kv.y);
            }
            float l0, h0, l1, h1; unpack2(a0, l0, h0); unpack2(a1, l1, h1);
            float part = (l0 + h0) + (l1 + h1);
            if ((mk >> kk) & 1u) part = neg_inf();
            float s = part + __shfl_xor_sync(0xffffffffu, part, 1);
            sreg[kk] = s;
            if (dh == 0) Ssh[h * SSTR + q * 9 + kk] = s;
        }
    };

    // =================== prologue ===================
    // K(0) -> Kbuf0
    if (t == 0) mbar_expect(mb0, TILEB);
    if (t >= 16 && t < 32) {
        int h2 = t - 16;
        bulk_g2s(kbB + (0 * KVBUF + h2 * ROWF) * 4, kglob(h2, 0), ROWF * 4, mb0);
    }
    unsigned mkv = load_mask(0);
    mbar_wait(mb0, 0);                           // Kbuf0 resident (acquire)

    // group(0): V(0)->Vbuf0 + K(1)->Kbuf1, tracked by mbG0
    if (t == 0) mbar_expect(mbG0, 2 * TILEB);
    if (t < 16) {
        bulk_g2s(vbB + (0 * KVBUF + t * ROWF) * 4, vglob(t, 0), ROWF * 4, mbG0);
    } else if (t < 32) {
        int h2 = t - 16;
        bulk_g2s(kbB + (1 * KVBUF + h2 * ROWF) * 4, kglob(h2, TK), ROWF * 4, mbG0);
    }
    do_score(0, mkv);                            // scores of tile 0 -> Ssh, sreg
    mkv = load_mask(1);                          // mask for tile 1 (next scored)

    // =================== main loop ===================
    for (int cur = 0; cur < NKT; cur++) {
        __syncthreads();                         // (S) Ssh(cur) ready; also proves
                                                 //     old buffer reads finished
        // ---- head softmax over 16 h: ALL 512 threads, 4 heads each ----
        {
            const int item = t >> 2, sub = t & 3;
            const int q2 = item >> 3, kk2 = item & 7;
            const int sb = q2 * 9 + kk2;
            const int hbase = sub * 4;
            float s0 = Ssh[(hbase + 0) * SSTR + sb];
            float s1 = Ssh[(hbase + 1) * SSTR + sb];
            float s2 = Ssh[(hbase + 2) * SSTR + sb];
            float s3 = Ssh[(hbase + 3) * SSTR + sb];
            float m = fmaxf(fmaxf(s0, s1), fmaxf(s2, s3));
            m = fmaxf(m, __shfl_xor_sync(0xffffffffu, m, 1));
            m = fmaxf(m, __shfl_xor_sync(0xffffffffu, m, 2));
            float e = __expf(s0 - m) + __expf(s1 - m) + __expf(s2 - m) + __expf(s3 - m);
            e += __shfl_xor_sync(0xffffffffu, e, 1);
            e += __shfl_xor_sync(0xffffffffu, e, 2);
            if (sub == 0) {
                float2 mr;
                if (m == neg_inf()) { mr.x = 0.f; mr.y = 0.f; }
                else                { mr.x = m;   mr.y = 1.0f / e; }
                MRsh[sb] = mr;
            }
        }

        // wait group(cur): V[cur] and K[cur+1] resident
        mbar_wait((cur & 1) ? mbG1 : mbG0, (cur >> 1) & 1);
        __syncthreads();                         // (W) MRsh visible to all

        // ---- issue group(cur+1): V(cur+1) + K(cur+2) (hidden under fused) ----
        if (cur + 1 < NKT) {
            const uint32_t mbn = ((cur + 1) & 1) ? mbG1 : mbG0;
            const int nvb = (cur + 1) & 1;       // V buffer for cur+1
            const int nkb = cur & 1;             // K buffer for cur+2
            const uint32_t bytes = TILEB + ((cur + 2 < NKT) ? TILEB : 0);
            if (t == 0) mbar_expect(mbn, bytes);
            if (t < 16) {
                bulk_g2s(vbB + (nvb * KVBUF + t * ROWF) * 4,
                         vglob(t, (cur + 1) * TK), ROWF * 4, mbn);
            } else if (t < 32 && cur + 2 < NKT) {
                int h2 = t - 16;
                bulk_g2s(kbB + (nkb * KVBUF + h2 * ROWF) * 4,
                         kglob(h2, (cur + 2) * TK), ROWF * 4, mbn);
            }
        }
        unsigned mknext = (cur + 2 < NKT) ? load_mask(cur + 2) : 0u;

        // ---- fused phase: ctx(cur) + score(cur+1) ----
        const int vb2 = cur & 1;
        const int nb  = (cur + 1) & 1;
        const bool do_sc = (cur + 1 < NKT);
        #pragma unroll
        for (int kk = 0; kk < TK; kk++) {
            float2 mr = MRsh[q * 9 + kk];
            float w = __expf(sreg[kk] - mr.x) * mr.y;
            u64 wp = pack2(w, w);
            const char* vbp = reinterpret_cast<const char*>(
                &Vb[vb2 * KVBUF + h * ROWF + kk * Dd]);
            #pragma unroll
            for (int i = 0; i < 8; i++) {
                ulonglong2 vv = *reinterpret_cast<const ulonglong2*>(vbp + i * 32 + dhb);
                ffma2(ctx[2*i],   wp, vv.x);
                ffma2(ctx[2*i+1], wp, vv.y);
            }
            if (do_sc) {
                const char* kbp = reinterpret_cast<const char*>(
                    &Kb[nb * KVBUF + h * ROWF + kk * Dd]);
                u64 a0 = 0ull, a1 = 0ull;
                #pragma unroll
                for (int i = 0; i < 8; i++) {
                    ulonglong2 kv = *reinterpret_cast<const ulonglong2*>(kbp + i * 32 + dhb);
                    ffma2(a0, Qp[2*i],   kv.x);
                    ffma2(a1, Qp[2*i+1], kv.y);
                }
                float l0, h0, l1, h1; unpack2(a0, l0, h0); unpack2(a1, l1, h1);
                float part = (l0 + h0) + (l1 + h1);
                if ((mkv >> kk) & 1u) part = neg_inf();
                float s = part + __shfl_xor_sync(0xffffffffu, part, 1);
                sreg[kk] = s;
                if (dh == 0) Ssh[h * SSTR + q * 9 + kk] = s;
            }
        }
        mkv = mknext;
    }

    // ---- epilogue: out[b, q0+q, h, chunks i*32B + dhb] = ctx ----
    char* obase = reinterpret_cast<char*>(
        Og + ((size_t)(b * Ss + (q0 + q)) * Hh + h) * Dd);
    #pragma unroll
    for (int i = 0; i < 8; i++) {
        ulonglong2 v; v.x = ctx[2*i]; v.y = ctx[2*i+1];
        *reinterpret_cast<ulonglong2*>(obase + i * 32 + dhb) = v;
    }
}

extern "C" void kernel_launch(void* const* d_in, const int* in_sizes, int n_in,
                              void* d_out, int out_size) {
    const float*         Q = (const float*)d_in[0];
    const float*         K = (const float*)d_in[1];
    const float*         V = (const float*)d_in[2];
    const unsigned char* M = (const unsigned char*)d_in[3];   // mask, dtype detected on-device
    // d_in[4] = head_dim (compile-time 64); unused.
    float* O = (float*)d_out;

    // 1) classify mask storage (element size). 256 KB sample, deterministic.
    detect_mask_kernel<<<1, 256>>>((const uint32_t*)M, 1 << 16);

    // 2) main attention kernel
    const size_t smem_bytes = (size_t)SMEM_FLOATS * sizeof(float);  // ~140 KB
    cudaFuncSetAttribute(attn_head_softmax_kernel,
                         cudaFuncAttributeMaxDynamicSharedMemorySize,
                         (int)smem_bytes);

    dim3 grid(Ss / TQ, Bb);   // (128, 2) = 256 CTAs of 512 threads
    attn_head_softmax_kernel<<<grid, NTH, smem_bytes>>>(Q, K, V, M, O);
}